// round 2
// baseline (speedup 1.0000x reference)
#include <cuda_runtime.h>
#include <math.h>

// Problem constants
#define BB 2
#define TT 2048
#define DD 1024
#define NH 16
#define HDIM 64
#define M_ROWS (BB*TT)          // 4096
#define N_QKV (3*DD)            // 3072

// ---------------- scratch (static device globals: allocation-free) ----------
__device__ float g_qkv[M_ROWS * N_QKV];            // 4096 x 3072
__device__ float g_q  [BB*NH*TT*HDIM];             // [B,H,T,HD]
__device__ float g_k  [BB*NH*TT*HDIM];
__device__ float g_v  [BB*NH*TT*HDIM];
__device__ float g_att[M_ROWS * DD];               // [B,T,D]

// ---------------- SGEMM: C[M,N] = A[M,K] @ B[K,N] + bias[N] -----------------
// BM=BN=64, BK=16, 256 threads, 4x4 microtile per thread.
__global__ __launch_bounds__(256) void sgemm_bias(
    const float* __restrict__ A, const float* __restrict__ Bm,
    const float* __restrict__ bias, float* __restrict__ C,
    int M, int N, int K)
{
    __shared__ float As[16][64];
    __shared__ float Bs[16][64];

    const int bx = blockIdx.x;   // N tile
    const int by = blockIdx.y;   // M tile
    const int tid = threadIdx.x;
    const int tx = tid & 15;
    const int ty = tid >> 4;

    const float* Aptr = A + (size_t)by * 64 * K;
    const float* Bptr = Bm + (size_t)bx * 64;

    const int arow = tid >> 2;        // 0..63
    const int acol = (tid & 3) * 4;   // 0,4,8,12
    const int brow = tid >> 4;        // 0..15
    const int bcol = (tid & 15) * 4;  // 0..60

    float acc[4][4];
#pragma unroll
    for (int i = 0; i < 4; i++)
#pragma unroll
        for (int j = 0; j < 4; j++) acc[i][j] = 0.f;

    for (int k0 = 0; k0 < K; k0 += 16) {
        float4 a4 = *(const float4*)(Aptr + (size_t)arow * K + k0 + acol);
        As[acol + 0][arow] = a4.x;
        As[acol + 1][arow] = a4.y;
        As[acol + 2][arow] = a4.z;
        As[acol + 3][arow] = a4.w;
        float4 b4 = *(const float4*)(Bptr + (size_t)(k0 + brow) * N + bcol);
        *(float4*)&Bs[brow][bcol] = b4;
        __syncthreads();

#pragma unroll
        for (int k = 0; k < 16; k++) {
            float ar[4], br[4];
#pragma unroll
            for (int i = 0; i < 4; i++) ar[i] = As[k][ty * 4 + i];
#pragma unroll
            for (int j = 0; j < 4; j++) br[j] = Bs[k][tx * 4 + j];
#pragma unroll
            for (int i = 0; i < 4; i++)
#pragma unroll
                for (int j = 0; j < 4; j++) acc[i][j] += ar[i] * br[j];
        }
        __syncthreads();
    }

#pragma unroll
    for (int i = 0; i < 4; i++) {
        int row = by * 64 + ty * 4 + i;
#pragma unroll
        for (int j = 0; j < 4; j++) {
            int col = bx * 64 + tx * 4 + j;
            C[(size_t)row * N + col] = acc[i][j] + bias[col];
        }
    }
}

// ---------------- RoPE + split to [B,H,T,HD] --------------------------------
// One thread per (b,t,h,i) with i = pair index 0..31.
__global__ __launch_bounds__(256) void rope_split_kernel(
    const float* __restrict__ qkv,
    float* __restrict__ Q, float* __restrict__ K, float* __restrict__ V)
{
    int idx = blockIdx.x * blockDim.x + threadIdx.x;  // B*T*H*32 total
    int i = idx & 31;
    int h = (idx >> 5) & (NH - 1);
    int t = (idx >> 9) & (TT - 1);
    int b = idx >> 20;

    const float* base = qkv + (size_t)(b * TT + t) * N_QKV;
    const float* qs = base + h * HDIM;
    const float* ks = base + DD + h * HDIM;
    const float* vs = base + 2 * DD + h * HDIM;

    float tf = (float)t;
    float sn, cs;
    if (i < 16) {
        float f1 = tf * powf(10000.f, -(float)(4 * i) / 64.f);
        float f2 = tf * powf(10000.f, -(float)(4 * i + 2) / 64.f);
        sn = sinf(f1);
        cs = sinf(f2);
    } else {
        float f1 = tf * powf(10000.f, -(float)(4 * i - 64) / 64.f);
        float f2 = tf * powf(10000.f, -(float)(4 * i - 62) / 64.f);
        sn = cosf(f1);
        cs = cosf(f2);
    }

    size_t obase = ((size_t)(b * NH + h) * TT + t) * HDIM;
    float q1 = qs[2 * i], q2 = qs[2 * i + 1];
    Q[obase + i]      = q1 * cs - q2 * sn;
    Q[obase + 32 + i] = q1 * sn + q2 * cs;
    float k1 = ks[2 * i], k2 = ks[2 * i + 1];
    K[obase + i]      = k1 * cs - k2 * sn;
    K[obase + 32 + i] = k1 * sn + k2 * cs;
    V[obase + 2 * i]     = vs[2 * i];
    V[obase + 2 * i + 1] = vs[2 * i + 1];
}

// ---------------- Causal flash attention ------------------------------------
// Block = 64 query rows of one (b,h); 64 threads, one query per thread.
// KV tiles of 32; K/V in shared, q/o/s in registers (float4-vectorized).
#define BQ 64
#define BKV 32

__global__ __launch_bounds__(64) void attn_kernel(
    const float* __restrict__ Q, const float* __restrict__ K,
    const float* __restrict__ V, float* __restrict__ O)
{
    const int qt = blockIdx.x;
    const int h = blockIdx.y;
    const int b = blockIdx.z;
    const int tid = threadIdx.x;
    const int qrow = qt * BQ + tid;

    const float* Qb = Q + (size_t)((b * NH + h) * TT) * HDIM;
    const float* Kb = K + (size_t)((b * NH + h) * TT) * HDIM;
    const float* Vb = V + (size_t)((b * NH + h) * TT) * HDIM;

    __shared__ float4 Ksh[BKV][HDIM / 4];
    __shared__ float4 Vsh[BKV][HDIM / 4];

    float4 q[16];
    const float4* qsrc = (const float4*)(Qb + (size_t)qrow * HDIM);
#pragma unroll
    for (int i = 0; i < 16; i++) q[i] = qsrc[i];

    float4 o[16];
#pragma unroll
    for (int i = 0; i < 16; i++) o[i] = make_float4(0.f, 0.f, 0.f, 0.f);
    float m = -1e30f, l = 0.f;
    const float scale = 0.125f;  // HD^-0.5

    const int kend = qt * BQ + BQ;
    for (int j0 = 0; j0 < kend; j0 += BKV) {
        // cooperative tile load: 64 threads, 32x64 floats per tile
        {
            int r = tid >> 1;
            int c0 = (tid & 1) * 8;
            const float4* ksrc = (const float4*)(Kb + (size_t)(j0 + r) * HDIM);
            const float4* vsrc = (const float4*)(Vb + (size_t)(j0 + r) * HDIM);
#pragma unroll
            for (int i = 0; i < 8; i++) {
                Ksh[r][c0 + i] = ksrc[c0 + i];
                Vsh[r][c0 + i] = vsrc[c0 + i];
            }
        }
        __syncthreads();

        float s[BKV];
#pragma unroll
        for (int j = 0; j < BKV; j++) s[j] = 0.f;
#pragma unroll
        for (int d4 = 0; d4 < 16; d4++) {
            float4 qv = q[d4];
#pragma unroll
            for (int j = 0; j < BKV; j++) {
                float4 kv = Ksh[j][d4];
                s[j] += qv.x * kv.x + qv.y * kv.y + qv.z * kv.z + qv.w * kv.w;
            }
        }

        float mt = m;
#pragma unroll
        for (int j = 0; j < BKV; j++) {
            s[j] = (j0 + j <= qrow) ? s[j] * scale : -1e30f;
            mt = fmaxf(mt, s[j]);
        }
        float alpha = __expf(m - mt);
        m = mt;
        l *= alpha;
#pragma unroll
        for (int i = 0; i < 16; i++) {
            o[i].x *= alpha; o[i].y *= alpha; o[i].z *= alpha; o[i].w *= alpha;
        }
#pragma unroll
        for (int j = 0; j < BKV; j++) {
            float p = __expf(s[j] - m);
            l += p;
#pragma unroll
            for (int d4 = 0; d4 < 16; d4++) {
                float4 vv = Vsh[j][d4];
                o[d4].x += p * vv.x; o[d4].y += p * vv.y;
                o[d4].z += p * vv.z; o[d4].w += p * vv.w;
            }
        }
        __syncthreads();
    }

    float inv = 1.f / l;
    float* dst = O + (size_t)(b * TT + qrow) * DD + h * HDIM;
#pragma unroll
    for (int i = 0; i < 16; i++) {
        float4 ov = o[i];
        ov.x *= inv; ov.y *= inv; ov.z *= inv; ov.w *= inv;
        ((float4*)dst)[i] = ov;
    }
}

// ---------------- launch -----------------------------------------------------
extern "C" void kernel_launch(void* const* d_in, const int* in_sizes, int n_in,
                              void* d_out, int out_size)
{
    const float* x     = (const float*)d_in[0];
    const float* qkv_w = (const float*)d_in[1];
    const float* qkv_b = (const float*)d_in[2];
    const float* out_w = (const float*)d_in[3];
    const float* out_b = (const float*)d_in[4];
    float* out = (float*)d_out;

    float *qkv, *q, *k, *v, *att;
    cudaGetSymbolAddress((void**)&qkv, g_qkv);
    cudaGetSymbolAddress((void**)&q,   g_q);
    cudaGetSymbolAddress((void**)&k,   g_k);
    cudaGetSymbolAddress((void**)&v,   g_v);
    cudaGetSymbolAddress((void**)&att, g_att);

    // 1) QKV projection: [4096,1024] @ [1024,3072] + b
    {
        dim3 grid(N_QKV / 64, M_ROWS / 64);
        sgemm_bias<<<grid, 256>>>(x, qkv_w, qkv_b, qkv, M_ROWS, N_QKV, DD);
    }
    // 2) RoPE + split into [B,H,T,HD]
    {
        int total = BB * TT * NH * 32;  // 2,097,152
        rope_split_kernel<<<total / 256, 256>>>(qkv, q, k, v);
    }
    // 3) Causal flash attention -> g_att [B,T,D]
    {
        dim3 grid(TT / BQ, NH, BB);
        attn_kernel<<<grid, 64>>>(q, k, v, att);
    }
    // 4) Output projection: [4096,1024] @ [1024,1024] + b
    {
        dim3 grid(DD / 64, M_ROWS / 64);
        sgemm_bias<<<grid, 256>>>(att, out_w, out_b, out, M_ROWS, DD, DD);
    }
}

// round 4
// speedup vs baseline: 1.5463x; 1.5463x over previous
#include <cuda_runtime.h>
#include <math.h>

// Problem constants
#define BB 2
#define TT 2048
#define DD 1024
#define NH 16
#define HDIM 64
#define M_ROWS (BB*TT)          // 4096
#define N_QKV (3*DD)            // 3072

// ---------------- scratch (static device globals: allocation-free) ----------
__device__ float g_qkv[M_ROWS * N_QKV];            // 4096 x 3072
__device__ float g_q  [BB*NH*TT*HDIM];             // [B,H,T,HD]
__device__ float g_k  [BB*NH*TT*HDIM];
__device__ float g_v  [BB*NH*TT*HDIM];
__device__ float g_att[M_ROWS * DD];               // [B,T,D]

// ---------------- SGEMM: C[M,N] = A[M,K] @ B[K,N] + bias[N] -----------------
// BM=BN=128, BK=16, 256 threads, 8x8 microtile per thread.
__global__ __launch_bounds__(256) void sgemm128(
    const float* __restrict__ A, const float* __restrict__ Bm,
    const float* __restrict__ bias, float* __restrict__ C,
    int M, int N, int K)
{
    __shared__ float As[16][128];   // transposed A tile
    __shared__ float Bs[16][128];

    const int tid = threadIdx.x;
    const int tx = tid & 15;        // N group
    const int ty = tid >> 4;        // M group
    const int bx = blockIdx.x;
    const int by = blockIdx.y;

    const float* Ap = A + (size_t)(by * 128) * K;
    const float* Bp = Bm + (size_t)(bx * 128);

    const int arow = tid >> 2;        // 0..63 (+64 second pass)
    const int acol = (tid & 3) * 4;   // 0,4,8,12
    const int brow = tid >> 4;        // 0..15
    const int bcol = (tid & 15) * 8;  // 0..120

    float acc[8][8];
#pragma unroll
    for (int i = 0; i < 8; i++)
#pragma unroll
        for (int j = 0; j < 8; j++) acc[i][j] = 0.f;

    for (int k0 = 0; k0 < K; k0 += 16) {
        // load A tile (128x16) transposed
#pragma unroll
        for (int r = 0; r < 2; r++) {
            float4 a4 = *(const float4*)(Ap + (size_t)(arow + r * 64) * K + k0 + acol);
            As[acol + 0][arow + r * 64] = a4.x;
            As[acol + 1][arow + r * 64] = a4.y;
            As[acol + 2][arow + r * 64] = a4.z;
            As[acol + 3][arow + r * 64] = a4.w;
        }
        // load B tile (16x128)
        {
            const float* bp = Bp + (size_t)(k0 + brow) * N + bcol;
            *(float4*)&Bs[brow][bcol]     = *(const float4*)(bp);
            *(float4*)&Bs[brow][bcol + 4] = *(const float4*)(bp + 4);
        }
        __syncthreads();

#pragma unroll
        for (int k = 0; k < 16; k++) {
            float ar[8], br[8];
            *(float4*)&ar[0] = *(const float4*)&As[k][ty * 8];
            *(float4*)&ar[4] = *(const float4*)&As[k][ty * 8 + 4];
            *(float4*)&br[0] = *(const float4*)&Bs[k][tx * 8];
            *(float4*)&br[4] = *(const float4*)&Bs[k][tx * 8 + 4];
#pragma unroll
            for (int i = 0; i < 8; i++)
#pragma unroll
                for (int j = 0; j < 8; j++) acc[i][j] += ar[i] * br[j];
        }
        __syncthreads();
    }

#pragma unroll
    for (int i = 0; i < 8; i++) {
        int row = by * 128 + ty * 8 + i;
        float* cp = C + (size_t)row * N + bx * 128 + tx * 8;
        const float* bp = bias + bx * 128 + tx * 8;
        float4 c0, c1;
        c0.x = acc[i][0] + bp[0]; c0.y = acc[i][1] + bp[1];
        c0.z = acc[i][2] + bp[2]; c0.w = acc[i][3] + bp[3];
        c1.x = acc[i][4] + bp[4]; c1.y = acc[i][5] + bp[5];
        c1.z = acc[i][6] + bp[6]; c1.w = acc[i][7] + bp[7];
        *(float4*)cp = c0;
        *(float4*)(cp + 4) = c1;
    }
}

// ---------------- RoPE + split to [B,H,T,HD] --------------------------------
__global__ __launch_bounds__(256) void rope_split_kernel(
    const float* __restrict__ qkv,
    float* __restrict__ Q, float* __restrict__ K, float* __restrict__ V)
{
    int idx = blockIdx.x * blockDim.x + threadIdx.x;  // B*T*H*32 total
    int i = idx & 31;
    int h = (idx >> 5) & (NH - 1);
    int t = (idx >> 9) & (TT - 1);
    int b = idx >> 20;

    const float* base = qkv + (size_t)(b * TT + t) * N_QKV;
    const float* qs = base + h * HDIM;
    const float* ks = base + DD + h * HDIM;
    const float* vs = base + 2 * DD + h * HDIM;

    float tf = (float)t;
    float sn, cs;
    if (i < 16) {
        float f1 = tf * powf(10000.f, -(float)(4 * i) / 64.f);
        float f2 = tf * powf(10000.f, -(float)(4 * i + 2) / 64.f);
        sn = sinf(f1);
        cs = sinf(f2);
    } else {
        float f1 = tf * powf(10000.f, -(float)(4 * i - 64) / 64.f);
        float f2 = tf * powf(10000.f, -(float)(4 * i - 62) / 64.f);
        sn = cosf(f1);
        cs = cosf(f2);
    }

    size_t obase = ((size_t)(b * NH + h) * TT + t) * HDIM;
    float q1 = qs[2 * i], q2 = qs[2 * i + 1];
    Q[obase + i]      = q1 * cs - q2 * sn;
    Q[obase + 32 + i] = q1 * sn + q2 * cs;
    float k1 = ks[2 * i], k2 = ks[2 * i + 1];
    K[obase + i]      = k1 * cs - k2 * sn;
    K[obase + 32 + i] = k1 * sn + k2 * cs;
    V[obase + 2 * i]     = vs[2 * i];
    V[obase + 2 * i + 1] = vs[2 * i + 1];
}

// ---------------- Causal flash attention (register-tiled) -------------------
// Block = 64 query rows of one (b,h), 256 threads (16x16 thread grid).
// Per tile: S = Q*K^T (4x4 per thread), online softmax with row state
// replicated across the 16 lanes of a row (shfl reductions), P staged in
// shared (aliased over the K^T tile), then O += P*V (4x4 per thread).
__global__ __launch_bounds__(256) void attn_kernel(
    const float* __restrict__ Q, const float* __restrict__ K,
    const float* __restrict__ V, float* __restrict__ O)
{
    __shared__ float Qs[64][64];    // Q tile, row-major, pre-scaled
    __shared__ float KPs[64][64];   // K^T tile [d][c]; reused as P [r][c]
    __shared__ float Vs[64][64];    // V tile [c][d]

    const int qt = blockIdx.x;
    const int h  = blockIdx.y;
    const int b  = blockIdx.z;
    const int tid = threadIdx.x;
    const int tx = tid & 15;        // KV-col / HD-col group
    const int ty = tid >> 4;        // Q-row group

    const size_t bh = (size_t)(b * NH + h) * TT * HDIM;
    const float* Qb = Q + bh;
    const float* Kb = K + bh;
    const float* Vb = V + bh;

    // Load Q tile, folding in the 1/sqrt(HD)=0.125 scale (exact power of 2)
    {
        int r  = tid >> 2;
        int d0 = (tid & 3) * 4;
        const float* src = Qb + (size_t)(qt * 64 + r) * HDIM;
#pragma unroll
        for (int cc = 0; cc < 4; cc++) {
            float4 v = *(const float4*)(src + d0 + cc * 16);
            v.x *= 0.125f; v.y *= 0.125f; v.z *= 0.125f; v.w *= 0.125f;
            *(float4*)&Qs[r][d0 + cc * 16] = v;
        }
    }

    float o[4][4];
#pragma unroll
    for (int i = 0; i < 4; i++)
#pragma unroll
        for (int j = 0; j < 4; j++) o[i][j] = 0.f;
    float m[4], l[4];
#pragma unroll
    for (int i = 0; i < 4; i++) { m[i] = -1e30f; l[i] = 0.f; }

    for (int jt = 0; jt <= qt; jt++) {
        const int j0 = jt * 64;
        __syncthreads();   // prev-tile PV reads done (also orders Q-tile load)

        // Load K tile transposed into KPs[d][c], V tile direct into Vs[c][d]
        {
            int c  = tid >> 2;
            int d0 = (tid & 3) * 4;
            const float* ks = Kb + (size_t)(j0 + c) * HDIM;
            const float* vs = Vb + (size_t)(j0 + c) * HDIM;
#pragma unroll
            for (int cc = 0; cc < 4; cc++) {
                float4 kv = *(const float4*)(ks + d0 + cc * 16);
                KPs[d0 + cc * 16 + 0][c] = kv.x;
                KPs[d0 + cc * 16 + 1][c] = kv.y;
                KPs[d0 + cc * 16 + 2][c] = kv.z;
                KPs[d0 + cc * 16 + 3][c] = kv.w;
                *(float4*)&Vs[c][d0 + cc * 16] = *(const float4*)(vs + d0 + cc * 16);
            }
        }
        __syncthreads();

        // S = Q*K^T : thread owns rows ty*4..+3, cols tx*4..+3
        float s[4][4];
#pragma unroll
        for (int i = 0; i < 4; i++)
#pragma unroll
            for (int j = 0; j < 4; j++) s[i][j] = 0.f;

#pragma unroll 4
        for (int k4 = 0; k4 < 16; k4++) {
            int k = k4 * 4;
            float4 a0 = *(const float4*)&Qs[ty * 4 + 0][k];
            float4 a1 = *(const float4*)&Qs[ty * 4 + 1][k];
            float4 a2 = *(const float4*)&Qs[ty * 4 + 2][k];
            float4 a3 = *(const float4*)&Qs[ty * 4 + 3][k];
            float4 b0 = *(const float4*)&KPs[k + 0][tx * 4];
            float4 b1 = *(const float4*)&KPs[k + 1][tx * 4];
            float4 b2 = *(const float4*)&KPs[k + 2][tx * 4];
            float4 b3 = *(const float4*)&KPs[k + 3][tx * 4];
            float bc[4][4] = {
                {b0.x, b0.y, b0.z, b0.w},
                {b1.x, b1.y, b1.z, b1.w},
                {b2.x, b2.y, b2.z, b2.w},
                {b3.x, b3.y, b3.z, b3.w}};
            float4 aa[4] = {a0, a1, a2, a3};
#pragma unroll
            for (int i = 0; i < 4; i++) {
                float4 av = aa[i];
#pragma unroll
                for (int j = 0; j < 4; j++) {
                    s[i][j] += av.x * bc[0][j];
                    s[i][j] += av.y * bc[1][j];
                    s[i][j] += av.z * bc[2][j];
                    s[i][j] += av.w * bc[3][j];
                }
            }
        }

        // Causal mask (diagonal tile only)
        if (jt == qt) {
#pragma unroll
            for (int i = 0; i < 4; i++) {
                int row = ty * 4 + i;   // local; global row = qt*64+row, col = j0+...
#pragma unroll
                for (int j = 0; j < 4; j++) {
                    int col = tx * 4 + j;
                    if (col > row) s[i][j] = -1e30f;
                }
            }
        }

        // Online softmax update; row state replicated across the 16 tx lanes
#pragma unroll
        for (int i = 0; i < 4; i++) {
            float rm = fmaxf(fmaxf(s[i][0], s[i][1]), fmaxf(s[i][2], s[i][3]));
#pragma unroll
            for (int w = 1; w < 16; w <<= 1)
                rm = fmaxf(rm, __shfl_xor_sync(0xffffffffu, rm, w));
            float mn = fmaxf(m[i], rm);
            float alpha = __expf(m[i] - mn);
            m[i] = mn;
            float rs = 0.f;
#pragma unroll
            for (int j = 0; j < 4; j++) {
                float p = __expf(s[i][j] - mn);
                s[i][j] = p;
                rs += p;
            }
#pragma unroll
            for (int w = 1; w < 16; w <<= 1)
                rs += __shfl_xor_sync(0xffffffffu, rs, w);
            l[i] = l[i] * alpha + rs;
#pragma unroll
            for (int j = 0; j < 4; j++) o[i][j] *= alpha;
        }

        __syncthreads();   // all S-GEMM reads of KPs complete before P overwrite

        // Stage P into shared (row-major, reusing KPs)
#pragma unroll
        for (int i = 0; i < 4; i++)
            *(float4*)&KPs[ty * 4 + i][tx * 4] =
                make_float4(s[i][0], s[i][1], s[i][2], s[i][3]);
        __syncthreads();

        // O += P * V
#pragma unroll 4
        for (int k4 = 0; k4 < 16; k4++) {
            int k = k4 * 4;
            float4 a0 = *(const float4*)&KPs[ty * 4 + 0][k];
            float4 a1 = *(const float4*)&KPs[ty * 4 + 1][k];
            float4 a2 = *(const float4*)&KPs[ty * 4 + 2][k];
            float4 a3 = *(const float4*)&KPs[ty * 4 + 3][k];
            float4 v0 = *(const float4*)&Vs[k + 0][tx * 4];
            float4 v1 = *(const float4*)&Vs[k + 1][tx * 4];
            float4 v2 = *(const float4*)&Vs[k + 2][tx * 4];
            float4 v3 = *(const float4*)&Vs[k + 3][tx * 4];
            float vc[4][4] = {
                {v0.x, v0.y, v0.z, v0.w},
                {v1.x, v1.y, v1.z, v1.w},
                {v2.x, v2.y, v2.z, v2.w},
                {v3.x, v3.y, v3.z, v3.w}};
            float4 aa[4] = {a0, a1, a2, a3};
#pragma unroll
            for (int i = 0; i < 4; i++) {
                float4 av = aa[i];
#pragma unroll
                for (int j = 0; j < 4; j++) {
                    o[i][j] += av.x * vc[0][j];
                    o[i][j] += av.y * vc[1][j];
                    o[i][j] += av.z * vc[2][j];
                    o[i][j] += av.w * vc[3][j];
                }
            }
        }
    }

    // Epilogue: normalize and write to [B,T,D]
#pragma unroll
    for (int i = 0; i < 4; i++) {
        float inv = 1.f / l[i];
        int row = qt * 64 + ty * 4 + i;
        float* dst = O + ((size_t)(b * TT + row)) * DD + h * HDIM + tx * 4;
        *(float4*)dst = make_float4(o[i][0] * inv, o[i][1] * inv,
                                    o[i][2] * inv, o[i][3] * inv);
    }
}

// ---------------- launch -----------------------------------------------------
extern "C" void kernel_launch(void* const* d_in, const int* in_sizes, int n_in,
                              void* d_out, int out_size)
{
    const float* x     = (const float*)d_in[0];
    const float* qkv_w = (const float*)d_in[1];
    const float* qkv_b = (const float*)d_in[2];
    const float* out_w = (const float*)d_in[3];
    const float* out_b = (const float*)d_in[4];
    float* out = (float*)d_out;

    float *qkv, *q, *k, *v, *att;
    cudaGetSymbolAddress((void**)&qkv, g_qkv);
    cudaGetSymbolAddress((void**)&q,   g_q);
    cudaGetSymbolAddress((void**)&k,   g_k);
    cudaGetSymbolAddress((void**)&v,   g_v);
    cudaGetSymbolAddress((void**)&att, g_att);

    // 1) QKV projection: [4096,1024] @ [1024,3072] + b
    {
        dim3 grid(N_QKV / 128, M_ROWS / 128);
        sgemm128<<<grid, 256>>>(x, qkv_w, qkv_b, qkv, M_ROWS, N_QKV, DD);
    }
    // 2) RoPE + split into [B,H,T,HD]
    {
        int total = BB * TT * NH * 32;  // 2,097,152
        rope_split_kernel<<<total / 256, 256>>>(qkv, q, k, v);
    }
    // 3) Causal flash attention -> g_att [B,T,D]
    {
        dim3 grid(TT / 64, NH, BB);
        attn_kernel<<<grid, 256>>>(q, k, v, att);
    }
    // 4) Output projection: [4096,1024] @ [1024,1024] + b
    {
        dim3 grid(DD / 128, M_ROWS / 128);
        sgemm128<<<grid, 256>>>(att, out_w, out_b, out, M_ROWS, DD, DD);
    }
}

// round 9
// speedup vs baseline: 2.1782x; 1.4086x over previous
#include <cuda_runtime.h>
#include <cuda_bf16.h>
#include <stdint.h>
#include <math.h>

// Problem constants
#define BB 2
#define TT 2048
#define DD 1024
#define NH 16
#define HDIM 64
#define M_ROWS (BB*TT)          // 4096
#define N_QKV (3*DD)            // 3072
#define K3 (3*DD)               // split-K' = 3*1024

// ---------------- scratch (static device globals: allocation-free) ----------
__device__ float g_qkv[M_ROWS * N_QKV];                    // 4096 x 3072 fp32
__device__ float g_q  [BB*NH*TT*HDIM];
__device__ float g_k  [BB*NH*TT*HDIM];
__device__ float g_v  [BB*NH*TT*HDIM];
__device__ float g_att[M_ROWS * DD];
__device__ __nv_bfloat16 g_a3 [M_ROWS * K3];               // [M, 3K] split A (reused)
__device__ __nv_bfloat16 g_bq3[N_QKV * K3];                // [N, 3K] split W_qkv^T
__device__ __nv_bfloat16 g_bo3[DD * K3];                   // [N, 3K] split W_out^T

// ======================= PTX helpers =========================================
__device__ __forceinline__ uint32_t smem_u32(const void* p) {
    uint32_t a;
    asm("{ .reg .u64 t; cvta.to.shared.u64 t, %1; cvt.u32.u64 %0, t; }"
        : "=r"(a) : "l"(p));
    return a;
}
#define CP_ASYNC16(dst, src) \
    asm volatile("cp.async.cg.shared.global [%0], [%1], 16;" \
                 :: "r"(dst), "l"(src) : "memory")
#define CP_COMMIT() asm volatile("cp.async.commit_group;" ::: "memory")
#define CP_WAIT1()  asm volatile("cp.async.wait_group 1;" ::: "memory")
#define CP_WAIT0()  asm volatile("cp.async.wait_group 0;" ::: "memory")

__device__ __forceinline__ void ldm_x4(uint32_t* r, uint32_t a) {
    asm volatile("ldmatrix.sync.aligned.m8n8.x4.shared.b16 {%0,%1,%2,%3}, [%4];"
                 : "=r"(r[0]), "=r"(r[1]), "=r"(r[2]), "=r"(r[3]) : "r"(a));
}
__device__ __forceinline__ void mma16816(float* c, const uint32_t* a,
                                         const uint32_t* b) {
    asm volatile(
        "mma.sync.aligned.m16n8k16.row.col.f32.bf16.bf16.f32 "
        "{%0,%1,%2,%3}, {%4,%5,%6,%7}, {%8,%9}, {%0,%1,%2,%3};"
        : "+f"(c[0]), "+f"(c[1]), "+f"(c[2]), "+f"(c[3])
        : "r"(a[0]), "r"(a[1]), "r"(a[2]), "r"(a[3]), "r"(b[0]), "r"(b[1]));
}

// ======================= split / transpose kernels ===========================
// A3[m, 0:K)=hi, [K:2K)=hi, [2K:3K)=lo   (K = DD = 1024)
__global__ __launch_bounds__(256) void split_a(
    const float* __restrict__ A, __nv_bfloat16* __restrict__ A3, int total)
{
    int idx = blockIdx.x * blockDim.x + threadIdx.x;
    if (idx >= total) return;
    int m = idx / DD, k = idx - m * DD;
    float a = A[idx];
    __nv_bfloat16 hi = __float2bfloat16(a);
    __nv_bfloat16 lo = __float2bfloat16(a - __bfloat162float(hi));
    size_t rb = (size_t)m * K3;
    A3[rb + k] = hi;
    A3[rb + DD + k] = hi;
    A3[rb + 2 * DD + k] = lo;
}

// W[K,N] fp32 -> Bt3[N, 3K] bf16: [0:K)=hi, [K:2K)=lo, [2K:3K)=hi
__global__ __launch_bounds__(256) void split_bt(
    const float* __restrict__ W, __nv_bfloat16* __restrict__ Bt3, int N)
{
    __shared__ float tile[32][33];
    int n0 = blockIdx.x * 32;
    int k0 = blockIdx.y * 32;
    int tx = threadIdx.x & 31;
    int ty = threadIdx.x >> 5;      // 0..7
    for (int r = ty; r < 32; r += 8)
        tile[r][tx] = W[(size_t)(k0 + r) * N + n0 + tx];
    __syncthreads();
    for (int r = ty; r < 32; r += 8) {
        int n = n0 + r;
        int k = k0 + tx;
        float w = tile[tx][r];
        __nv_bfloat16 hi = __float2bfloat16(w);
        __nv_bfloat16 lo = __float2bfloat16(w - __bfloat162float(hi));
        size_t rb = (size_t)n * K3;
        Bt3[rb + k] = hi;
        Bt3[rb + DD + k] = lo;
        Bt3[rb + 2 * DD + k] = hi;
    }
}

// ======================= mma.sync GEMM =======================================
// C[M,N] = A3[M,K3] * Bt3[N,K3]^T + bias.
// Block 128x128, 8 warps (2x4), warp tile 64x32, K-chunk 32, 2-stage cp.async.
#define SM_STRIDE 40    // bf16 elements per smem row (conflict-free for ldmatrix)

__global__ __launch_bounds__(256, 2) void gemm_mma(
    const __nv_bfloat16* __restrict__ A, const __nv_bfloat16* __restrict__ Bt,
    const float* __restrict__ bias, float* __restrict__ C, int N)
{
    __shared__ __nv_bfloat16 sh[2][2][128][SM_STRIDE];  // [stage][A=0/B=1]

    const int tid = threadIdx.x;
    const int lane = tid & 31;
    const int wid = tid >> 5;
    const int wm = wid >> 2;        // 0..1
    const int wn = wid & 3;         // 0..3
    const int bm = blockIdx.y;
    const int bn = blockIdx.x;
    const int KCH = K3 / 32;        // 96

    const uint32_t shA0 = smem_u32(&sh[0][0][0][0]);
    const uint32_t stageBytes = 2 * 128 * SM_STRIDE * 2;   // A+B per stage
    const uint32_t abBytes = 128 * SM_STRIDE * 2;

    // producer indices: g = tid + 256*i (i<2): row = g>>2, seg = g&3 (8 bf16)
    const int prow = tid >> 2;
    const int pseg = (tid & 3) * 8;
    const size_t arow0 = (size_t)(bm * 128 + prow) * K3 + pseg;
    const size_t brow0 = (size_t)(bn * 128 + prow) * K3 + pseg;
    const size_t arow1 = (size_t)(bm * 128 + prow + 64) * K3 + pseg;
    const size_t brow1 = (size_t)(bn * 128 + prow + 64) * K3 + pseg;
    const uint32_t dA0 = (prow * SM_STRIDE + pseg) * 2;
    const uint32_t dA1 = ((prow + 64) * SM_STRIDE + pseg) * 2;

    float c[4][4][4];
#pragma unroll
    for (int i = 0; i < 4; i++)
#pragma unroll
        for (int j = 0; j < 4; j++)
#pragma unroll
            for (int r = 0; r < 4; r++) c[i][j][r] = 0.f;

    // ldmatrix lane addressing (byte offsets into a stage's A or B region)
    const int lr = lane & 7;
    const int sel = lane >> 3;
    // A x4: matrices (m0-7,k0-7),(m8-15,k0-7),(m0-7,k8-15),(m8-15,k8-15)
    const uint32_t aRow = wm * 64 + lr + ((sel & 1) << 3);
    const uint32_t aCol = (sel >> 1) << 3;
    const uint32_t aOff = (aRow * SM_STRIDE + aCol) * 2;
    // B x4 (two n8 tiles per load): (n0-7,k0-7),(n0-7,k8-15),(n8-15,k0-7),(n8-15,k8-15)
    const uint32_t bRow = wn * 32 + lr + ((sel >> 1) << 3);
    const uint32_t bCol = (sel & 1) << 3;
    const uint32_t bOff = (bRow * SM_STRIDE + bCol) * 2;

    // issue chunk 0
    {
        const __nv_bfloat16* a0 = A + arow0;
        const __nv_bfloat16* b0 = Bt + brow0;
        CP_ASYNC16(shA0 + dA0, a0);
        CP_ASYNC16(shA0 + abBytes + dA0, b0);
        CP_ASYNC16(shA0 + dA1, A + arow1);
        CP_ASYNC16(shA0 + abBytes + dA1, Bt + brow1);
        CP_COMMIT();
    }

    for (int kc = 0; kc < KCH; kc++) {
        if (kc + 1 < KCH) {
            uint32_t sb = shA0 + ((kc + 1) & 1) * stageBytes;
            size_t ko = (size_t)(kc + 1) * 32;
            CP_ASYNC16(sb + dA0, A + arow0 + ko);
            CP_ASYNC16(sb + abBytes + dA0, Bt + brow0 + ko);
            CP_ASYNC16(sb + dA1, A + arow1 + ko);
            CP_ASYNC16(sb + abBytes + dA1, Bt + brow1 + ko);
            CP_COMMIT();
            CP_WAIT1();
        } else {
            CP_WAIT0();
        }
        __syncthreads();

        uint32_t sb = shA0 + (kc & 1) * stageBytes;
#pragma unroll
        for (int ks = 0; ks < 2; ks++) {             // two k16 steps
            uint32_t af[4][4], bf[4][2];
#pragma unroll
            for (int mi = 0; mi < 4; mi++)
                ldm_x4(af[mi], sb + aOff + (mi * 16 * SM_STRIDE + ks * 16) * 2);
#pragma unroll
            for (int p = 0; p < 2; p++) {
                uint32_t r4[4];
                ldm_x4(r4, sb + abBytes + bOff +
                           (p * 16 * SM_STRIDE + ks * 16) * 2);
                bf[p * 2][0] = r4[0]; bf[p * 2][1] = r4[1];
                bf[p * 2 + 1][0] = r4[2]; bf[p * 2 + 1][1] = r4[3];
            }
#pragma unroll
            for (int mi = 0; mi < 4; mi++)
#pragma unroll
                for (int nj = 0; nj < 4; nj++)
                    mma16816(c[mi][nj], af[mi], bf[nj]);
        }
        __syncthreads();
    }

    // epilogue: add bias, write fp32
    const int cn0 = bn * 128 + wn * 32 + (lane & 3) * 2;
    const int cm0 = bm * 128 + wm * 64 + (lane >> 2);
#pragma unroll
    for (int nj = 0; nj < 4; nj++) {
        int col = cn0 + nj * 8;
        float bv0 = bias[col], bv1 = bias[col + 1];
#pragma unroll
        for (int mi = 0; mi < 4; mi++) {
            int row = cm0 + mi * 16;
            float2 v0 = make_float2(c[mi][nj][0] + bv0, c[mi][nj][1] + bv1);
            float2 v1 = make_float2(c[mi][nj][2] + bv0, c[mi][nj][3] + bv1);
            *(float2*)(C + (size_t)row * N + col) = v0;
            *(float2*)(C + (size_t)(row + 8) * N + col) = v1;
        }
    }
}

// ---------------- RoPE + split to [B,H,T,HD] --------------------------------
__global__ __launch_bounds__(256) void rope_split_kernel(
    const float* __restrict__ qkv,
    float* __restrict__ Q, float* __restrict__ K, float* __restrict__ V)
{
    int idx = blockIdx.x * blockDim.x + threadIdx.x;
    int i = idx & 31;
    int h = (idx >> 5) & (NH - 1);
    int t = (idx >> 9) & (TT - 1);
    int b = idx >> 20;

    const float* base = qkv + (size_t)(b * TT + t) * N_QKV;
    const float* qs = base + h * HDIM;
    const float* ks = base + DD + h * HDIM;
    const float* vs = base + 2 * DD + h * HDIM;

    float tf = (float)t;
    float sn, cs;
    if (i < 16) {
        float f1 = tf * powf(10000.f, -(float)(4 * i) / 64.f);
        float f2 = tf * powf(10000.f, -(float)(4 * i + 2) / 64.f);
        sn = sinf(f1);
        cs = sinf(f2);
    } else {
        float f1 = tf * powf(10000.f, -(float)(4 * i - 64) / 64.f);
        float f2 = tf * powf(10000.f, -(float)(4 * i - 62) / 64.f);
        sn = cosf(f1);
        cs = cosf(f2);
    }

    size_t obase = ((size_t)(b * NH + h) * TT + t) * HDIM;
    float q1 = qs[2 * i], q2 = qs[2 * i + 1];
    Q[obase + i]      = q1 * cs - q2 * sn;
    Q[obase + 32 + i] = q1 * sn + q2 * cs;
    float k1 = ks[2 * i], k2 = ks[2 * i + 1];
    K[obase + i]      = k1 * cs - k2 * sn;
    K[obase + 32 + i] = k1 * sn + k2 * cs;
    V[obase + 2 * i]     = vs[2 * i];
    V[obase + 2 * i + 1] = vs[2 * i + 1];
}

// ---------------- Causal flash attention (register-tiled) -------------------
__global__ __launch_bounds__(256) void attn_kernel(
    const float* __restrict__ Q, const float* __restrict__ K,
    const float* __restrict__ V, float* __restrict__ O)
{
    __shared__ float Qs[64][64];
    __shared__ float KPs[64][64];
    __shared__ float Vs[64][64];

    const int qt = blockIdx.x;
    const int h  = blockIdx.y;
    const int b  = blockIdx.z;
    const int tid = threadIdx.x;
    const int tx = tid & 15;
    const int ty = tid >> 4;

    const size_t bh = (size_t)(b * NH + h) * TT * HDIM;
    const float* Qb = Q + bh;
    const float* Kb = K + bh;
    const float* Vb = V + bh;

    {
        int r  = tid >> 2;
        int d0 = (tid & 3) * 4;
        const float* src = Qb + (size_t)(qt * 64 + r) * HDIM;
#pragma unroll
        for (int cc = 0; cc < 4; cc++) {
            float4 v = *(const float4*)(src + d0 + cc * 16);
            v.x *= 0.125f; v.y *= 0.125f; v.z *= 0.125f; v.w *= 0.125f;
            *(float4*)&Qs[r][d0 + cc * 16] = v;
        }
    }

    float o[4][4];
#pragma unroll
    for (int i = 0; i < 4; i++)
#pragma unroll
        for (int j = 0; j < 4; j++) o[i][j] = 0.f;
    float m[4], l[4];
#pragma unroll
    for (int i = 0; i < 4; i++) { m[i] = -1e30f; l[i] = 0.f; }

    for (int jt = 0; jt <= qt; jt++) {
        const int j0 = jt * 64;
        __syncthreads();
        {
            int c  = tid >> 2;
            int d0 = (tid & 3) * 4;
            const float* ks = Kb + (size_t)(j0 + c) * HDIM;
            const float* vs = Vb + (size_t)(j0 + c) * HDIM;
#pragma unroll
            for (int cc = 0; cc < 4; cc++) {
                float4 kv = *(const float4*)(ks + d0 + cc * 16);
                KPs[d0 + cc * 16 + 0][c] = kv.x;
                KPs[d0 + cc * 16 + 1][c] = kv.y;
                KPs[d0 + cc * 16 + 2][c] = kv.z;
                KPs[d0 + cc * 16 + 3][c] = kv.w;
                *(float4*)&Vs[c][d0 + cc * 16] = *(const float4*)(vs + d0 + cc * 16);
            }
        }
        __syncthreads();

        float s[4][4];
#pragma unroll
        for (int i = 0; i < 4; i++)
#pragma unroll
            for (int j = 0; j < 4; j++) s[i][j] = 0.f;

#pragma unroll 4
        for (int k4 = 0; k4 < 16; k4++) {
            int k = k4 * 4;
            float4 a0 = *(const float4*)&Qs[ty * 4 + 0][k];
            float4 a1 = *(const float4*)&Qs[ty * 4 + 1][k];
            float4 a2 = *(const float4*)&Qs[ty * 4 + 2][k];
            float4 a3 = *(const float4*)&Qs[ty * 4 + 3][k];
            float4 b0 = *(const float4*)&KPs[k + 0][tx * 4];
            float4 b1 = *(const float4*)&KPs[k + 1][tx * 4];
            float4 b2 = *(const float4*)&KPs[k + 2][tx * 4];
            float4 b3 = *(const float4*)&KPs[k + 3][tx * 4];
            float bc[4][4] = {
                {b0.x, b0.y, b0.z, b0.w},
                {b1.x, b1.y, b1.z, b1.w},
                {b2.x, b2.y, b2.z, b2.w},
                {b3.x, b3.y, b3.z, b3.w}};
            float4 aa[4] = {a0, a1, a2, a3};
#pragma unroll
            for (int i = 0; i < 4; i++) {
                float4 av = aa[i];
#pragma unroll
                for (int j = 0; j < 4; j++) {
                    s[i][j] += av.x * bc[0][j];
                    s[i][j] += av.y * bc[1][j];
                    s[i][j] += av.z * bc[2][j];
                    s[i][j] += av.w * bc[3][j];
                }
            }
        }

        if (jt == qt) {
#pragma unroll
            for (int i = 0; i < 4; i++) {
                int row = ty * 4 + i;
#pragma unroll
                for (int j = 0; j < 4; j++) {
                    int col = tx * 4 + j;
                    if (col > row) s[i][j] = -1e30f;
                }
            }
        }

#pragma unroll
        for (int i = 0; i < 4; i++) {
            float rm = fmaxf(fmaxf(s[i][0], s[i][1]), fmaxf(s[i][2], s[i][3]));
#pragma unroll
            for (int w = 1; w < 16; w <<= 1)
                rm = fmaxf(rm, __shfl_xor_sync(0xffffffffu, rm, w));
            float mn = fmaxf(m[i], rm);
            float alpha = __expf(m[i] - mn);
            m[i] = mn;
            float rs = 0.f;
#pragma unroll
            for (int j = 0; j < 4; j++) {
                float p = __expf(s[i][j] - mn);
                s[i][j] = p;
                rs += p;
            }
#pragma unroll
            for (int w = 1; w < 16; w <<= 1)
                rs += __shfl_xor_sync(0xffffffffu, rs, w);
            l[i] = l[i] * alpha + rs;
#pragma unroll
            for (int j = 0; j < 4; j++) o[i][j] *= alpha;
        }

        __syncthreads();

#pragma unroll
        for (int i = 0; i < 4; i++)
            *(float4*)&KPs[ty * 4 + i][tx * 4] =
                make_float4(s[i][0], s[i][1], s[i][2], s[i][3]);
        __syncthreads();

#pragma unroll 4
        for (int k4 = 0; k4 < 16; k4++) {
            int k = k4 * 4;
            float4 a0 = *(const float4*)&KPs[ty * 4 + 0][k];
            float4 a1 = *(const float4*)&KPs[ty * 4 + 1][k];
            float4 a2 = *(const float4*)&KPs[ty * 4 + 2][k];
            float4 a3 = *(const float4*)&KPs[ty * 4 + 3][k];
            float4 v0 = *(const float4*)&Vs[k + 0][tx * 4];
            float4 v1 = *(const float4*)&Vs[k + 1][tx * 4];
            float4 v2 = *(const float4*)&Vs[k + 2][tx * 4];
            float4 v3 = *(const float4*)&Vs[k + 3][tx * 4];
            float vc[4][4] = {
                {v0.x, v0.y, v0.z, v0.w},
                {v1.x, v1.y, v1.z, v1.w},
                {v2.x, v2.y, v2.z, v2.w},
                {v3.x, v3.y, v3.z, v3.w}};
            float4 aa[4] = {a0, a1, a2, a3};
#pragma unroll
            for (int i = 0; i < 4; i++) {
                float4 av = aa[i];
#pragma unroll
                for (int j = 0; j < 4; j++) {
                    o[i][j] += av.x * vc[0][j];
                    o[i][j] += av.y * vc[1][j];
                    o[i][j] += av.z * vc[2][j];
                    o[i][j] += av.w * vc[3][j];
                }
            }
        }
    }

#pragma unroll
    for (int i = 0; i < 4; i++) {
        float inv = 1.f / l[i];
        int row = qt * 64 + ty * 4 + i;
        float* dst = O + ((size_t)(b * TT + row)) * DD + h * HDIM + tx * 4;
        *(float4*)dst = make_float4(o[i][0] * inv, o[i][1] * inv,
                                    o[i][2] * inv, o[i][3] * inv);
    }
}

// ---------------- launch -----------------------------------------------------
extern "C" void kernel_launch(void* const* d_in, const int* in_sizes, int n_in,
                              void* d_out, int out_size)
{
    const float* x     = (const float*)d_in[0];
    const float* qkv_w = (const float*)d_in[1];
    const float* qkv_b = (const float*)d_in[2];
    const float* out_w = (const float*)d_in[3];
    const float* out_b = (const float*)d_in[4];
    float* out = (float*)d_out;

    float *qkv, *q, *k, *v, *att;
    __nv_bfloat16 *a3, *bq3, *bo3;
    cudaGetSymbolAddress((void**)&qkv, g_qkv);
    cudaGetSymbolAddress((void**)&q,   g_q);
    cudaGetSymbolAddress((void**)&k,   g_k);
    cudaGetSymbolAddress((void**)&v,   g_v);
    cudaGetSymbolAddress((void**)&att, g_att);
    cudaGetSymbolAddress((void**)&a3,  g_a3);
    cudaGetSymbolAddress((void**)&bq3, g_bq3);
    cudaGetSymbolAddress((void**)&bo3, g_bo3);

    // 0) bf16 hi/lo splits of x and W_qkv^T
    split_a<<<(M_ROWS * DD) / 256, 256>>>(x, a3, M_ROWS * DD);
    {
        dim3 g(N_QKV / 32, DD / 32);
        split_bt<<<g, 256>>>(qkv_w, bq3, N_QKV);
    }
    // 1) QKV projection via mma.sync
    {
        dim3 grid(N_QKV / 128, M_ROWS / 128);
        gemm_mma<<<grid, 256>>>(a3, bq3, qkv_b, qkv, N_QKV);
    }
    // 2) RoPE + split
    rope_split_kernel<<<(BB * TT * NH * 32) / 256, 256>>>(qkv, q, k, v);
    // 3) Causal flash attention
    {
        dim3 grid(TT / 64, NH, BB);
        attn_kernel<<<grid, 256>>>(q, k, v, att);
    }
    // 4) Output projection via mma.sync (reuse a3 for split of att)
    split_a<<<(M_ROWS * DD) / 256, 256>>>(att, a3, M_ROWS * DD);
    {
        dim3 g(DD / 32, DD / 32);
        split_bt<<<g, 256>>>(out_w, bo3, DD);
    }
    {
        dim3 grid(DD / 128, M_ROWS / 128);
        gemm_mma<<<grid, 256>>>(a3, bo3, out_b, out, DD);
    }
}

// round 10
// speedup vs baseline: 3.4133x; 1.5670x over previous
#include <cuda_runtime.h>
#include <cuda_bf16.h>
#include <stdint.h>
#include <math.h>

// Problem constants
#define BB 2
#define TT 2048
#define DD 1024
#define NH 16
#define HDIM 64
#define M_ROWS (BB*TT)          // 4096
#define N_QKV (3*DD)            // 3072
#define K3 (3*DD)               // split-K' = 3*1024
#define BH (BB*NH)              // 32

// ---------------- scratch (static device globals: allocation-free) ----------
__device__ float g_qkv[M_ROWS * N_QKV];                    // 4096 x 3072 fp32
__device__ float g_att[M_ROWS * DD];
__device__ __nv_bfloat16 g_a3 [M_ROWS * K3];               // [M, 3K] split A (reused)
__device__ __nv_bfloat16 g_bq3[N_QKV * K3];                // [N, 3K] split W_qkv^T
__device__ __nv_bfloat16 g_bo3[DD * K3];                   // [N, 3K] split W_out^T
__device__ __nv_bfloat16 g_q3 [BH * TT * 192];             // [bh][t][192] split Q (scaled)
__device__ __nv_bfloat16 g_k3 [BH * TT * 192];             // [bh][t][192] split K
__device__ __nv_bfloat16 g_vth[BH * HDIM * TT];            // [bh][d][t] V hi (transposed)
__device__ __nv_bfloat16 g_vtl[BH * HDIM * TT];            // [bh][d][t] V lo

// ======================= PTX helpers =========================================
__device__ __forceinline__ uint32_t smem_u32(const void* p) {
    uint32_t a;
    asm("{ .reg .u64 t; cvta.to.shared.u64 t, %1; cvt.u32.u64 %0, t; }"
        : "=r"(a) : "l"(p));
    return a;
}
#define CP_ASYNC16(dst, src) \
    asm volatile("cp.async.cg.shared.global [%0], [%1], 16;" \
                 :: "r"(dst), "l"(src) : "memory")
#define CP_COMMIT() asm volatile("cp.async.commit_group;" ::: "memory")
#define CP_WAIT1()  asm volatile("cp.async.wait_group 1;" ::: "memory")
#define CP_WAIT0()  asm volatile("cp.async.wait_group 0;" ::: "memory")

__device__ __forceinline__ void ldm_x4(uint32_t* r, uint32_t a) {
    asm volatile("ldmatrix.sync.aligned.m8n8.x4.shared.b16 {%0,%1,%2,%3}, [%4];"
                 : "=r"(r[0]), "=r"(r[1]), "=r"(r[2]), "=r"(r[3]) : "r"(a));
}
__device__ __forceinline__ void mma16816(float* c, const uint32_t* a,
                                         const uint32_t* b) {
    asm volatile(
        "mma.sync.aligned.m16n8k16.row.col.f32.bf16.bf16.f32 "
        "{%0,%1,%2,%3}, {%4,%5,%6,%7}, {%8,%9}, {%0,%1,%2,%3};"
        : "+f"(c[0]), "+f"(c[1]), "+f"(c[2]), "+f"(c[3])
        : "r"(a[0]), "r"(a[1]), "r"(a[2]), "r"(a[3]), "r"(b[0]), "r"(b[1]));
}
// pack {lo=trunc_bf16(a), hi=trunc_bf16(b)} in one PRMT
__device__ __forceinline__ uint32_t prmt_hi16(float a, float b) {
    uint32_t r;
    asm("prmt.b32 %0, %1, %2, 0x7632;"
        : "=r"(r) : "r"(__float_as_uint(a)), "r"(__float_as_uint(b)));
    return r;
}
__device__ __forceinline__ uint32_t pack_bf16(float lo, float hi) {
    uint32_t r;
    asm("cvt.rn.bf16x2.f32 %0, %1, %2;" : "=r"(r) : "f"(hi), "f"(lo));
    return r;
}
__device__ __forceinline__ float trunc_bf(float a) {
    return __uint_as_float(__float_as_uint(a) & 0xFFFF0000u);
}
// fast 2^t for t <= 0 on FMA/ALU pipes (no MUFU). |rel err| ~2e-6.
__device__ __forceinline__ float exp2p(float t) {
    t = fmaxf(t, -30.f);
    float fm = t + 12582912.f;                       // round-to-nearest int
    int n = __float_as_int(fm) - 0x4B400000;
    float f = t - (fm - 12582912.f);                 // [-0.5, 0.5]
    float p = 0.0013333558f;
    p = fmaf(p, f, 0.0096181291f);
    p = fmaf(p, f, 0.0555041087f);
    p = fmaf(p, f, 0.2402265069f);
    p = fmaf(p, f, 0.6931471806f);
    p = fmaf(p, f, 1.0f);
    return p * __int_as_float((n + 127) << 23);
}

// ======================= split / transpose kernels ===========================
__global__ __launch_bounds__(256) void split_a(
    const float* __restrict__ A, __nv_bfloat16* __restrict__ A3, int total)
{
    int idx = blockIdx.x * blockDim.x + threadIdx.x;
    if (idx >= total) return;
    int m = idx / DD, k = idx - m * DD;
    float a = A[idx];
    __nv_bfloat16 hi = __float2bfloat16(a);
    __nv_bfloat16 lo = __float2bfloat16(a - __bfloat162float(hi));
    size_t rb = (size_t)m * K3;
    A3[rb + k] = hi;
    A3[rb + DD + k] = hi;
    A3[rb + 2 * DD + k] = lo;
}

__global__ __launch_bounds__(256) void split_bt(
    const float* __restrict__ W, __nv_bfloat16* __restrict__ Bt3, int N)
{
    __shared__ float tile[32][33];
    int n0 = blockIdx.x * 32;
    int k0 = blockIdx.y * 32;
    int tx = threadIdx.x & 31;
    int ty = threadIdx.x >> 5;
    for (int r = ty; r < 32; r += 8)
        tile[r][tx] = W[(size_t)(k0 + r) * N + n0 + tx];
    __syncthreads();
    for (int r = ty; r < 32; r += 8) {
        int n = n0 + r;
        int k = k0 + tx;
        float w = tile[tx][r];
        __nv_bfloat16 hi = __float2bfloat16(w);
        __nv_bfloat16 lo = __float2bfloat16(w - __bfloat162float(hi));
        size_t rb = (size_t)n * K3;
        Bt3[rb + k] = hi;
        Bt3[rb + DD + k] = lo;
        Bt3[rb + 2 * DD + k] = hi;
    }
}

// ======================= mma.sync GEMM (unchanged from R9) ===================
#define SM_STRIDE 40

__global__ __launch_bounds__(256, 2) void gemm_mma(
    const __nv_bfloat16* __restrict__ A, const __nv_bfloat16* __restrict__ Bt,
    const float* __restrict__ bias, float* __restrict__ C, int N)
{
    __shared__ __nv_bfloat16 sh[2][2][128][SM_STRIDE];

    const int tid = threadIdx.x;
    const int lane = tid & 31;
    const int wid = tid >> 5;
    const int wm = wid >> 2;
    const int wn = wid & 3;
    const int bm = blockIdx.y;
    const int bn = blockIdx.x;
    const int KCH = K3 / 32;

    const uint32_t shA0 = smem_u32(&sh[0][0][0][0]);
    const uint32_t stageBytes = 2 * 128 * SM_STRIDE * 2;
    const uint32_t abBytes = 128 * SM_STRIDE * 2;

    const int prow = tid >> 2;
    const int pseg = (tid & 3) * 8;
    const size_t arow0 = (size_t)(bm * 128 + prow) * K3 + pseg;
    const size_t brow0 = (size_t)(bn * 128 + prow) * K3 + pseg;
    const size_t arow1 = (size_t)(bm * 128 + prow + 64) * K3 + pseg;
    const size_t brow1 = (size_t)(bn * 128 + prow + 64) * K3 + pseg;
    const uint32_t dA0 = (prow * SM_STRIDE + pseg) * 2;
    const uint32_t dA1 = ((prow + 64) * SM_STRIDE + pseg) * 2;

    float c[4][4][4];
#pragma unroll
    for (int i = 0; i < 4; i++)
#pragma unroll
        for (int j = 0; j < 4; j++)
#pragma unroll
            for (int r = 0; r < 4; r++) c[i][j][r] = 0.f;

    const int lr = lane & 7;
    const int sel = lane >> 3;
    const uint32_t aRow = wm * 64 + lr + ((sel & 1) << 3);
    const uint32_t aCol = (sel >> 1) << 3;
    const uint32_t aOff = (aRow * SM_STRIDE + aCol) * 2;
    const uint32_t bRow = wn * 32 + lr + ((sel >> 1) << 3);
    const uint32_t bCol = (sel & 1) << 3;
    const uint32_t bOff = (bRow * SM_STRIDE + bCol) * 2;

    {
        CP_ASYNC16(shA0 + dA0, A + arow0);
        CP_ASYNC16(shA0 + abBytes + dA0, Bt + brow0);
        CP_ASYNC16(shA0 + dA1, A + arow1);
        CP_ASYNC16(shA0 + abBytes + dA1, Bt + brow1);
        CP_COMMIT();
    }

    for (int kc = 0; kc < KCH; kc++) {
        if (kc + 1 < KCH) {
            uint32_t sb = shA0 + ((kc + 1) & 1) * stageBytes;
            size_t ko = (size_t)(kc + 1) * 32;
            CP_ASYNC16(sb + dA0, A + arow0 + ko);
            CP_ASYNC16(sb + abBytes + dA0, Bt + brow0 + ko);
            CP_ASYNC16(sb + dA1, A + arow1 + ko);
            CP_ASYNC16(sb + abBytes + dA1, Bt + brow1 + ko);
            CP_COMMIT();
            CP_WAIT1();
        } else {
            CP_WAIT0();
        }
        __syncthreads();

        uint32_t sb = shA0 + (kc & 1) * stageBytes;
#pragma unroll
        for (int ks = 0; ks < 2; ks++) {
            uint32_t af[4][4], bf[4][2];
#pragma unroll
            for (int mi = 0; mi < 4; mi++)
                ldm_x4(af[mi], sb + aOff + (mi * 16 * SM_STRIDE + ks * 16) * 2);
#pragma unroll
            for (int p = 0; p < 2; p++) {
                uint32_t r4[4];
                ldm_x4(r4, sb + abBytes + bOff +
                           (p * 16 * SM_STRIDE + ks * 16) * 2);
                bf[p * 2][0] = r4[0]; bf[p * 2][1] = r4[1];
                bf[p * 2 + 1][0] = r4[2]; bf[p * 2 + 1][1] = r4[3];
            }
#pragma unroll
            for (int mi = 0; mi < 4; mi++)
#pragma unroll
                for (int nj = 0; nj < 4; nj++)
                    mma16816(c[mi][nj], af[mi], bf[nj]);
        }
        __syncthreads();
    }

    const int cn0 = bn * 128 + wn * 32 + (lane & 3) * 2;
    const int cm0 = bm * 128 + wm * 64 + (lane >> 2);
#pragma unroll
    for (int nj = 0; nj < 4; nj++) {
        int col = cn0 + nj * 8;
        float bv0 = bias[col], bv1 = bias[col + 1];
#pragma unroll
        for (int mi = 0; mi < 4; mi++) {
            int row = cm0 + mi * 16;
            float2 v0 = make_float2(c[mi][nj][0] + bv0, c[mi][nj][1] + bv1);
            float2 v1 = make_float2(c[mi][nj][2] + bv0, c[mi][nj][3] + bv1);
            *(float2*)(C + (size_t)row * N + col) = v0;
            *(float2*)(C + (size_t)(row + 8) * N + col) = v1;
        }
    }
}

// ---------------- RoPE -> split Q3/K3 ([bh][t][192] bf16) -------------------
// Q3 windows: [hi | hi | lo] (scaled by 0.125*log2(e));  K3: [hi | lo | hi].
__global__ __launch_bounds__(256) void rope_split2(
    const float* __restrict__ qkv,
    __nv_bfloat16* __restrict__ Q3, __nv_bfloat16* __restrict__ K3g)
{
    int idx = blockIdx.x * blockDim.x + threadIdx.x;
    int i = idx & 31;
    int h = (idx >> 5) & (NH - 1);
    int t = (idx >> 9) & (TT - 1);
    int b = idx >> 20;

    const float* base = qkv + (size_t)(b * TT + t) * N_QKV;
    const float* qs = base + h * HDIM;
    const float* ks = base + DD + h * HDIM;

    float tf = (float)t;
    float sn, cs;
    if (i < 16) {
        float f1 = tf * powf(10000.f, -(float)(4 * i) / 64.f);
        float f2 = tf * powf(10000.f, -(float)(4 * i + 2) / 64.f);
        sn = sinf(f1);
        cs = sinf(f2);
    } else {
        float f1 = tf * powf(10000.f, -(float)(4 * i - 64) / 64.f);
        float f2 = tf * powf(10000.f, -(float)(4 * i - 62) / 64.f);
        sn = cosf(f1);
        cs = cosf(f2);
    }

    const float QSC = 0.125f * 1.44269504f;   // scale * log2(e), folded into Q
    size_t ob = ((size_t)(b * NH + h) * TT + t) * 192;

    float q1 = qs[2 * i], q2 = qs[2 * i + 1];
    float qa = (q1 * cs - q2 * sn) * QSC;     // dim i
    float qb = (q1 * sn + q2 * cs) * QSC;     // dim 32+i
    __nv_bfloat16 qah = __float2bfloat16(qa);
    __nv_bfloat16 qbh = __float2bfloat16(qb);
    Q3[ob + i]       = qah;  Q3[ob + 64 + i]  = qah;
    Q3[ob + 128 + i] = __float2bfloat16(qa - __bfloat162float(qah));
    Q3[ob + 32 + i]  = qbh;  Q3[ob + 96 + i]  = qbh;
    Q3[ob + 160 + i] = __float2bfloat16(qb - __bfloat162float(qbh));

    float k1 = ks[2 * i], k2 = ks[2 * i + 1];
    float ka = k1 * cs - k2 * sn;
    float kb = k1 * sn + k2 * cs;
    __nv_bfloat16 kah = __float2bfloat16(ka);
    __nv_bfloat16 kbh = __float2bfloat16(kb);
    K3g[ob + i]       = kah;
    K3g[ob + 64 + i]  = __float2bfloat16(ka - __bfloat162float(kah));
    K3g[ob + 128 + i] = kah;
    K3g[ob + 32 + i]  = kbh;
    K3g[ob + 96 + i]  = __float2bfloat16(kb - __bfloat162float(kbh));
    K3g[ob + 160 + i] = kbh;
}

// ---------------- V transpose + hi/lo split: [bh][d][t] ---------------------
__global__ __launch_bounds__(256) void vsplit_t(
    const float* __restrict__ qkv,
    __nv_bfloat16* __restrict__ Vh, __nv_bfloat16* __restrict__ Vl)
{
    __shared__ float tile[32][33];
    int t0 = blockIdx.x * 32;
    int d0 = blockIdx.y * 32;
    int bh = blockIdx.z;
    int b = bh >> 4, h = bh & 15;
    int tx = threadIdx.x & 31;
    int ty = threadIdx.x >> 5;
    const float* src = qkv + ((size_t)(b * TT) + t0) * N_QKV + 2 * DD + h * HDIM + d0;
    for (int r = ty; r < 32; r += 8)
        tile[r][tx] = src[(size_t)r * N_QKV + tx];
    __syncthreads();
    for (int r = ty; r < 32; r += 8) {
        float v = tile[tx][r];                   // t = t0+tx, d = d0+r
        __nv_bfloat16 hi = __float2bfloat16(v);
        size_t o = ((size_t)bh * HDIM + d0 + r) * TT + t0 + tx;
        Vh[o] = hi;
        Vl[o] = __float2bfloat16(v - __bfloat162float(hi));
    }
}

// ======================= mma.sync flash attention ============================
// Block = 128 q rows of one (b,h); 8 warps, m16 each; KV tiles of 64.
#define QSTR 200                 // padded bf16 stride (conflict-free ldmatrix)
#define KSTR 200
#define VSTR 72
#define ATT_STG 44032            // K 25600 + Vh 9216 + Vl 9216
#define ATT_SMEM (2 * ATT_STG)   // 88064

__global__ __launch_bounds__(256, 1) void attn_mma(
    const __nv_bfloat16* __restrict__ Q3, const __nv_bfloat16* __restrict__ K3g,
    const __nv_bfloat16* __restrict__ Vh, const __nv_bfloat16* __restrict__ Vl,
    float* __restrict__ O)
{
    extern __shared__ char smem[];
    const uint32_t su = smem_u32(smem);
    const int tid = threadIdx.x;
    const int lane = tid & 31;
    const int wm = tid >> 5;        // warp = 16 q rows
    const int qt = blockIdx.x;
    const int bh = blockIdx.y;
    const int q0 = qt * 128;
    const int jmax = 2 * qt + 2;

    const __nv_bfloat16* Qg  = Q3  + (size_t)bh * TT * 192;
    const __nv_bfloat16* Kg  = K3g + (size_t)bh * TT * 192;
    const __nv_bfloat16* Vhg = Vh  + (size_t)bh * HDIM * TT;
    const __nv_bfloat16* Vlg = Vl  + (size_t)bh * HDIM * TT;

    // ---- stage Q tile (128 x 192) and extract A-fragments, then free smem
#pragma unroll
    for (int c = 0; c < 12; c++) {
        int g = tid + 256 * c;
        int row = g / 24, seg = g % 24;
        CP_ASYNC16(su + row * (QSTR * 2) + seg * 16,
                   Qg + (size_t)(q0 + row) * 192 + seg * 8);
    }
    CP_COMMIT(); CP_WAIT0();
    __syncthreads();

    const int lr = lane & 7;
    const int sel = lane >> 3;
    uint32_t qf[12][4];
    {
        uint32_t ab = su + (wm * 16 + lr + ((sel & 1) << 3)) * (QSTR * 2)
                    + (((sel >> 1) << 3)) * 2;
#pragma unroll
        for (int kk = 0; kk < 12; kk++)
            ldm_x4(qf[kk], ab + kk * 32);
    }
    __syncthreads();

    float oacc[8][4];
#pragma unroll
    for (int i = 0; i < 8; i++)
#pragma unroll
        for (int j = 0; j < 4; j++) oacc[i][j] = 0.f;
    float mrow0 = -1e30f, mrow1 = -1e30f, lrow0 = 0.f, lrow1 = 0.f;

    auto issue = [&](int jt2) {
        int j0p = jt2 * 64;
        uint32_t sb = su + (jt2 & 1) * ATT_STG;
#pragma unroll
        for (int c = 0; c < 6; c++) {
            int g = tid + 256 * c;
            int row = g / 24, seg = g % 24;
            CP_ASYNC16(sb + row * (KSTR * 2) + seg * 16,
                       Kg + (size_t)(j0p + row) * 192 + seg * 8);
        }
#pragma unroll
        for (int c = 0; c < 2; c++) {
            int g = tid + 256 * c;
            int row = g >> 3, seg = g & 7;
            CP_ASYNC16(sb + 25600 + row * (VSTR * 2) + seg * 16,
                       Vhg + (size_t)row * TT + j0p + seg * 8);
            CP_ASYNC16(sb + 34816 + row * (VSTR * 2) + seg * 16,
                       Vlg + (size_t)row * TT + j0p + seg * 8);
        }
    };

    issue(0); CP_COMMIT();

    for (int jt = 0; jt < jmax; jt++) {
        if (jt + 1 < jmax) { issue(jt + 1); CP_COMMIT(); CP_WAIT1(); }
        else CP_WAIT0();
        __syncthreads();

        const int j0 = jt * 64;
        if (j0 <= q0 + wm * 16 + 15) {          // warp has unmasked work
            uint32_t sb = su + (jt & 1) * ATT_STG;

            // ---- S = Q K^T (n = kv cols 0..63)
            float sacc[8][4];
#pragma unroll
            for (int i = 0; i < 8; i++)
#pragma unroll
                for (int j = 0; j < 4; j++) sacc[i][j] = 0.f;

            uint32_t kb = sb + (lr + ((sel >> 1) << 3)) * (KSTR * 2)
                        + (((sel & 1) << 3)) * 2;
#pragma unroll
            for (int kk = 0; kk < 12; kk++) {
#pragma unroll
                for (int w = 0; w < 4; w++) {
                    uint32_t r4[4];
                    ldm_x4(r4, kb + (w * 16) * (KSTR * 2) + kk * 32);
                    mma16816(sacc[2 * w],     qf[kk], r4);
                    mma16816(sacc[2 * w + 1], qf[kk], r4 + 2);
                }
            }

            // ---- causal mask (diagonal region only)
            int r0 = q0 + wm * 16 + (lane >> 2);
            if (j0 + 63 > q0 + wm * 16) {
#pragma unroll
                for (int nt = 0; nt < 8; nt++) {
                    int cb = j0 + nt * 8 + (lane & 3) * 2;
                    if (cb     > r0)     sacc[nt][0] = -1e30f;
                    if (cb + 1 > r0)     sacc[nt][1] = -1e30f;
                    if (cb     > r0 + 8) sacc[nt][2] = -1e30f;
                    if (cb + 1 > r0 + 8) sacc[nt][3] = -1e30f;
                }
            }

            // ---- online softmax (base-2, poly exp on FMA pipe)
            float mx0 = -1e30f, mx1 = -1e30f;
#pragma unroll
            for (int nt = 0; nt < 8; nt++) {
                mx0 = fmaxf(mx0, fmaxf(sacc[nt][0], sacc[nt][1]));
                mx1 = fmaxf(mx1, fmaxf(sacc[nt][2], sacc[nt][3]));
            }
            mx0 = fmaxf(mx0, __shfl_xor_sync(0xffffffffu, mx0, 1));
            mx0 = fmaxf(mx0, __shfl_xor_sync(0xffffffffu, mx0, 2));
            mx1 = fmaxf(mx1, __shfl_xor_sync(0xffffffffu, mx1, 1));
            mx1 = fmaxf(mx1, __shfl_xor_sync(0xffffffffu, mx1, 2));
            float mn0 = fmaxf(mrow0, mx0), mn1 = fmaxf(mrow1, mx1);
            float a0 = exp2p(mrow0 - mn0), a1 = exp2p(mrow1 - mn1);
            mrow0 = mn0; mrow1 = mn1;
            lrow0 *= a0; lrow1 *= a1;
#pragma unroll
            for (int nt = 0; nt < 8; nt++) {
                oacc[nt][0] *= a0; oacc[nt][1] *= a0;
                oacc[nt][2] *= a1; oacc[nt][3] *= a1;
            }
            float rs0 = 0.f, rs1 = 0.f;
#pragma unroll
            for (int nt = 0; nt < 8; nt++) {
                sacc[nt][0] = exp2p(sacc[nt][0] - mn0);
                sacc[nt][1] = exp2p(sacc[nt][1] - mn0);
                sacc[nt][2] = exp2p(sacc[nt][2] - mn1);
                sacc[nt][3] = exp2p(sacc[nt][3] - mn1);
                rs0 += sacc[nt][0] + sacc[nt][1];
                rs1 += sacc[nt][2] + sacc[nt][3];
            }
            rs0 += __shfl_xor_sync(0xffffffffu, rs0, 1);
            rs0 += __shfl_xor_sync(0xffffffffu, rs0, 2);
            rs1 += __shfl_xor_sync(0xffffffffu, rs1, 1);
            rs1 += __shfl_xor_sync(0xffffffffu, rs1, 2);
            lrow0 += rs0; lrow1 += rs1;

            // ---- pack P hi (truncate) / lo into A-fragments
            uint32_t ah[4][4], al[4][4];
#pragma unroll
            for (int k2 = 0; k2 < 4; k2++) {
                float p00 = sacc[2 * k2][0],     p01 = sacc[2 * k2][1];
                float p02 = sacc[2 * k2][2],     p03 = sacc[2 * k2][3];
                float p10 = sacc[2 * k2 + 1][0], p11 = sacc[2 * k2 + 1][1];
                float p12 = sacc[2 * k2 + 1][2], p13 = sacc[2 * k2 + 1][3];
                ah[k2][0] = prmt_hi16(p00, p01);
                ah[k2][1] = prmt_hi16(p02, p03);
                ah[k2][2] = prmt_hi16(p10, p11);
                ah[k2][3] = prmt_hi16(p12, p13);
                al[k2][0] = pack_bf16(p00 - trunc_bf(p00), p01 - trunc_bf(p01));
                al[k2][1] = pack_bf16(p02 - trunc_bf(p02), p03 - trunc_bf(p03));
                al[k2][2] = pack_bf16(p10 - trunc_bf(p10), p11 - trunc_bf(p11));
                al[k2][3] = pack_bf16(p12 - trunc_bf(p12), p13 - trunc_bf(p13));
            }

            // ---- O += P V  (3-term: Ph*Vh + Pl*Vh + Ph*Vl), n = hd cols
            uint32_t vb = sb + 25600 + (lr + ((sel >> 1) << 3)) * (VSTR * 2)
                        + (((sel & 1) << 3)) * 2;
#pragma unroll
            for (int k2 = 0; k2 < 4; k2++) {
#pragma unroll
                for (int w = 0; w < 4; w++) {
                    uint32_t v4[4];
                    ldm_x4(v4, vb + (w * 16) * (VSTR * 2) + k2 * 32);
                    mma16816(oacc[2 * w],     ah[k2], v4);
                    mma16816(oacc[2 * w + 1], ah[k2], v4 + 2);
                    mma16816(oacc[2 * w],     al[k2], v4);
                    mma16816(oacc[2 * w + 1], al[k2], v4 + 2);
                    ldm_x4(v4, vb + 9216 + (w * 16) * (VSTR * 2) + k2 * 32);
                    mma16816(oacc[2 * w],     ah[k2], v4);
                    mma16816(oacc[2 * w + 1], ah[k2], v4 + 2);
                }
            }
        }
        __syncthreads();
    }

    // ---- epilogue
    float inv0 = 1.f / lrow0, inv1 = 1.f / lrow1;
    int b = bh >> 4, h = bh & 15;
    int r0 = q0 + wm * 16 + (lane >> 2);
#pragma unroll
    for (int nt = 0; nt < 8; nt++) {
        int col = h * HDIM + nt * 8 + (lane & 3) * 2;
        *(float2*)(O + (size_t)(b * TT + r0) * DD + col) =
            make_float2(oacc[nt][0] * inv0, oacc[nt][1] * inv0);
        *(float2*)(O + (size_t)(b * TT + r0 + 8) * DD + col) =
            make_float2(oacc[nt][2] * inv1, oacc[nt][3] * inv1);
    }
}

// ---------------- launch -----------------------------------------------------
extern "C" void kernel_launch(void* const* d_in, const int* in_sizes, int n_in,
                              void* d_out, int out_size)
{
    const float* x     = (const float*)d_in[0];
    const float* qkv_w = (const float*)d_in[1];
    const float* qkv_b = (const float*)d_in[2];
    const float* out_w = (const float*)d_in[3];
    const float* out_b = (const float*)d_in[4];
    float* out = (float*)d_out;

    float *qkv, *att;
    __nv_bfloat16 *a3, *bq3, *bo3, *q3, *k3, *vth, *vtl;
    cudaGetSymbolAddress((void**)&qkv, g_qkv);
    cudaGetSymbolAddress((void**)&att, g_att);
    cudaGetSymbolAddress((void**)&a3,  g_a3);
    cudaGetSymbolAddress((void**)&bq3, g_bq3);
    cudaGetSymbolAddress((void**)&bo3, g_bo3);
    cudaGetSymbolAddress((void**)&q3,  g_q3);
    cudaGetSymbolAddress((void**)&k3,  g_k3);
    cudaGetSymbolAddress((void**)&vth, g_vth);
    cudaGetSymbolAddress((void**)&vtl, g_vtl);

    cudaFuncSetAttribute(attn_mma, cudaFuncAttributeMaxDynamicSharedMemorySize,
                         ATT_SMEM);

    // 0) bf16 hi/lo splits of x and W_qkv^T
    split_a<<<(M_ROWS * DD) / 256, 256>>>(x, a3, M_ROWS * DD);
    {
        dim3 g(N_QKV / 32, DD / 32);
        split_bt<<<g, 256>>>(qkv_w, bq3, N_QKV);
    }
    // 1) QKV projection via mma.sync
    {
        dim3 grid(N_QKV / 128, M_ROWS / 128);
        gemm_mma<<<grid, 256>>>(a3, bq3, qkv_b, qkv, N_QKV);
    }
    // 2) RoPE + split Q/K ; V transpose + split
    rope_split2<<<(BB * TT * NH * 32) / 256, 256>>>(qkv, q3, k3);
    {
        dim3 g(TT / 32, HDIM / 32, BH);
        vsplit_t<<<g, 256>>>(qkv, vth, vtl);
    }
    // 3) mma.sync flash attention
    {
        dim3 grid(TT / 128, BH);
        attn_mma<<<grid, 256, ATT_SMEM>>>(q3, k3, vth, vtl, att);
    }
    // 4) Output projection via mma.sync
    split_a<<<(M_ROWS * DD) / 256, 256>>>(att, a3, M_ROWS * DD);
    {
        dim3 g(DD / 32, DD / 32);
        split_bt<<<g, 256>>>(out_w, bo3, DD);
    }
    {
        dim3 grid(DD / 128, M_ROWS / 128);
        gemm_mma<<<grid, 256>>>(a3, bo3, out_b, out, DD);
    }
}